// round 2
// baseline (speedup 1.0000x reference)
#include <cuda_runtime.h>
#include <cuda_bf16.h>

// Problem constants (fixed by reference setup_inputs):
//   src_feat [50000,128] f32, dst_feat [50000,128] f32,
//   att_w [256,1] f32, att_b [1] f32,
//   edge_index [2,640000] int32 (JAX x64 disabled downgrades int64->int32),
//   n_dst scalar (unused; derived from out_size).
#define DIMS 128
#define NMAX 50048   // slack over 50000

__device__ float g_srcdot[NMAX];
__device__ float g_dstdot[NMAX];   // includes +bias
__device__ float g_count[NMAX];

// ---------------------------------------------------------------------------
// Kernel 1: per-row dot products with the attention weight halves.
// One warp per row; lane l holds float4 l of the 128-float row.
// ---------------------------------------------------------------------------
__global__ void dot_kernel(const float* __restrict__ src_feat,
                           const float* __restrict__ dst_feat,
                           const float* __restrict__ att_w,
                           const float* __restrict__ att_b,
                           int n_src, int n_dst) {
    int wid  = (blockIdx.x * blockDim.x + threadIdx.x) >> 5;
    int lane = threadIdx.x & 31;
    int total = n_src + n_dst;
    if (wid >= total) return;

    bool is_src = (wid < n_src);
    int row = is_src ? wid : (wid - n_src);
    const float* feat = is_src ? src_feat : dst_feat;
    const float* w    = att_w + (is_src ? 0 : DIMS);

    float4 f  = ((const float4*)(feat + (size_t)row * DIMS))[lane];
    float4 wv = ((const float4*)w)[lane];
    float s = f.x * wv.x + f.y * wv.y + f.z * wv.z + f.w * wv.w;

    #pragma unroll
    for (int o = 16; o > 0; o >>= 1)
        s += __shfl_down_sync(0xffffffffu, s, o);

    if (lane == 0) {
        if (is_src) g_srcdot[row] = s;
        else        g_dstdot[row] = s + att_b[0];
    }
}

// ---------------------------------------------------------------------------
// Kernel 2: edge pass. One warp per edge.
//   att = sigmoid(srcdot[s] + dstdot[d])
//   agg[d] += att * src_feat[s]   (4x atomicAdd.f32 per lane, coalesced 512B)
//   count[d] += att               (lane 0)
// ---------------------------------------------------------------------------
__global__ void edge_kernel(const float* __restrict__ src_feat,
                            const int* __restrict__ edge_index,
                            float* __restrict__ agg,
                            int n_edges) {
    int wid  = (blockIdx.x * blockDim.x + threadIdx.x) >> 5;
    int lane = threadIdx.x & 31;
    if (wid >= n_edges) return;

    int s = edge_index[wid];            // src index (row 0)
    int d = edge_index[n_edges + wid];  // dst index (row 1)

    float logit = g_srcdot[s] + g_dstdot[d];
    float att = 1.0f / (1.0f + __expf(-logit));

    float4 v = ((const float4*)(src_feat + (size_t)s * DIMS))[lane];

    float* out = agg + (size_t)d * DIMS + lane * 4;
    atomicAdd(out + 0, v.x * att);
    atomicAdd(out + 1, v.y * att);
    atomicAdd(out + 2, v.z * att);
    atomicAdd(out + 3, v.w * att);

    if (lane == 0) atomicAdd(&g_count[d], att);
}

// ---------------------------------------------------------------------------
// Kernel 3: normalize agg by per-dst attention mass.
// ---------------------------------------------------------------------------
__global__ void norm_kernel(float* __restrict__ out, int n_dst) {
    int tid = blockIdx.x * blockDim.x + threadIdx.x;
    int total = n_dst * DIMS;
    if (tid >= total) return;
    float c = g_count[tid >> 7];  // tid / 128
    out[tid] = out[tid] / fmaxf(c, 1e-8f);
}

// ---------------------------------------------------------------------------
extern "C" void kernel_launch(void* const* d_in, const int* in_sizes, int n_in,
                              void* d_out, int out_size) {
    const float* src_feat   = (const float*)d_in[0];
    const float* dst_feat   = (const float*)d_in[1];
    const float* att_w      = (const float*)d_in[2];
    const float* att_b      = (const float*)d_in[3];
    const int*   edge_index = (const int*)d_in[4];

    int n_src   = in_sizes[0] / DIMS;
    int n_dst   = out_size    / DIMS;
    int n_edges = in_sizes[4] / 2;

    float* agg = (float*)d_out;

    // Zero the accumulators (d_out is poisoned; g_count persists across calls).
    void* count_ptr = nullptr;
    cudaGetSymbolAddress(&count_ptr, g_count);
    cudaMemsetAsync(agg, 0, (size_t)out_size * sizeof(float), 0);
    cudaMemsetAsync(count_ptr, 0, (size_t)n_dst * sizeof(float), 0);

    // K1: per-row dot products (one warp per row).
    {
        int warps = n_src + n_dst;
        int threads = 256;
        int blocks = (warps * 32 + threads - 1) / threads;
        dot_kernel<<<blocks, threads>>>(src_feat, dst_feat, att_w, att_b,
                                        n_src, n_dst);
    }

    // K2: edge scatter (one warp per edge).
    {
        int threads = 256;
        int warps_per_block = threads / 32;
        int blocks = (n_edges + warps_per_block - 1) / warps_per_block;
        edge_kernel<<<blocks, threads>>>(src_feat, edge_index, agg, n_edges);
    }

    // K3: normalize.
    {
        int total = n_dst * DIMS;
        int threads = 256;
        int blocks = (total + threads - 1) / threads;
        norm_kernel<<<blocks, threads>>>(agg, n_dst);
    }
}

// round 3
// speedup vs baseline: 1.5294x; 1.5294x over previous
#include <cuda_runtime.h>
#include <cuda_bf16.h>

// Problem constants (fixed by reference setup_inputs):
//   src_feat [50000,128] f32, dst_feat [50000,128] f32,
//   att_w [256,1] f32, att_b [1] f32,
//   edge_index [2,640000] int32 (JAX x64-off downgrades int64->int32),
//   n_dst scalar (unused; derived from out_size).
#define DIMS 128
#define NMAX 50176    // slack over 50000
#define EMAX 700000   // slack over 640000
#define SCAN_THREADS 1024

__device__ float g_srcdot[NMAX];
__device__ float g_dstdot[NMAX];      // includes +bias
__device__ int   g_counts[NMAX];
__device__ int   g_offsets[NMAX + 1];
__device__ int   g_cursor[NMAX];
__device__ int   g_es[EMAX];          // bucketed src index per edge
__device__ float g_ea[EMAX];          // bucketed attention per edge

// ---------------------------------------------------------------------------
// K1: per-row dot products with attention weight halves. One warp per row.
// ---------------------------------------------------------------------------
__global__ void dot_kernel(const float* __restrict__ src_feat,
                           const float* __restrict__ dst_feat,
                           const float* __restrict__ att_w,
                           const float* __restrict__ att_b,
                           int n_src, int n_dst) {
    int wid  = (blockIdx.x * blockDim.x + threadIdx.x) >> 5;
    int lane = threadIdx.x & 31;
    int total = n_src + n_dst;
    if (wid >= total) return;

    bool is_src = (wid < n_src);
    int row = is_src ? wid : (wid - n_src);
    const float* feat = is_src ? src_feat : dst_feat;
    const float* w    = att_w + (is_src ? 0 : DIMS);

    float4 f  = ((const float4*)(feat + (size_t)row * DIMS))[lane];
    float4 wv = ((const float4*)w)[lane];
    float s = f.x * wv.x + f.y * wv.y + f.z * wv.z + f.w * wv.w;

    #pragma unroll
    for (int o = 16; o > 0; o >>= 1)
        s += __shfl_down_sync(0xffffffffu, s, o);

    if (lane == 0) {
        if (is_src) g_srcdot[row] = s;
        else        g_dstdot[row] = s + att_b[0];
    }
}

// ---------------------------------------------------------------------------
// K2: histogram of dst degrees.
// ---------------------------------------------------------------------------
__global__ void hist_kernel(const int* __restrict__ edge_index, int n_edges) {
    int i = blockIdx.x * blockDim.x + threadIdx.x;
    if (i >= n_edges) return;
    atomicAdd(&g_counts[edge_index[n_edges + i]], 1);
}

// ---------------------------------------------------------------------------
// K3: single-block exclusive scan of counts -> offsets (+ cursor copy).
// Thread t owns a contiguous chunk of C elements.
// ---------------------------------------------------------------------------
__global__ void scan_kernel(int n_dst) {
    const int C = (n_dst + SCAN_THREADS - 1) / SCAN_THREADS;
    int t    = threadIdx.x;
    int lane = t & 31;
    int w    = t >> 5;
    int base = t * C;

    int local = 0;
    for (int i = 0; i < C; i++) {
        int idx = base + i;
        if (idx < n_dst) local += g_counts[idx];
    }

    // block exclusive scan of per-thread sums
    __shared__ int warp_sums[32];
    int x = local;
    #pragma unroll
    for (int o = 1; o < 32; o <<= 1) {
        int y = __shfl_up_sync(0xffffffffu, x, o);
        if (lane >= o) x += y;
    }
    if (lane == 31) warp_sums[w] = x;
    __syncthreads();
    if (w == 0) {
        int v = warp_sums[lane];
        #pragma unroll
        for (int o = 1; o < 32; o <<= 1) {
            int y = __shfl_up_sync(0xffffffffu, v, o);
            if (lane >= o) v += y;
        }
        warp_sums[lane] = v;
    }
    __syncthreads();
    int run = (x - local) + (w > 0 ? warp_sums[w - 1] : 0);

    for (int i = 0; i < C; i++) {
        int idx = base + i;
        if (idx < n_dst) {
            g_offsets[idx] = run;
            g_cursor[idx]  = run;
            run += g_counts[idx];
        }
    }
    if (t == SCAN_THREADS - 1) g_offsets[n_dst] = run;  // == total edges
}

// ---------------------------------------------------------------------------
// K4: scatter edges into dst buckets with precomputed attention.
// ---------------------------------------------------------------------------
__global__ void scatter_kernel(const int* __restrict__ edge_index, int n_edges) {
    int i = blockIdx.x * blockDim.x + threadIdx.x;
    if (i >= n_edges) return;
    int s = edge_index[i];
    int d = edge_index[n_edges + i];
    float logit = g_srcdot[s] + g_dstdot[d];
    float att = 1.0f / (1.0f + __expf(-logit));
    int pos = atomicAdd(&g_cursor[d], 1);
    g_es[pos] = s;
    g_ea[pos] = att;
}

// ---------------------------------------------------------------------------
// K5: warp-per-dst aggregation + fused normalize. No float atomics.
// Lane l owns float4 l of the 128-float row; 2-wide unroll for MLP.
// ---------------------------------------------------------------------------
__global__ void agg_kernel(const float* __restrict__ src_feat,
                           float* __restrict__ out, int n_dst) {
    int wid  = (blockIdx.x * blockDim.x + threadIdx.x) >> 5;
    int lane = threadIdx.x & 31;
    if (wid >= n_dst) return;

    int start = g_offsets[wid];
    int end   = g_offsets[wid + 1];

    float4 acc = make_float4(0.f, 0.f, 0.f, 0.f);
    float attsum = 0.f;

    const float4* sf4 = (const float4*)src_feat;

    int e = start;
    for (; e + 1 < end; e += 2) {
        int   s0 = g_es[e];
        float a0 = g_ea[e];
        int   s1 = g_es[e + 1];
        float a1 = g_ea[e + 1];
        float4 v0 = sf4[(size_t)s0 * 32 + lane];
        float4 v1 = sf4[(size_t)s1 * 32 + lane];
        acc.x = fmaf(a0, v0.x, acc.x); acc.y = fmaf(a0, v0.y, acc.y);
        acc.z = fmaf(a0, v0.z, acc.z); acc.w = fmaf(a0, v0.w, acc.w);
        acc.x = fmaf(a1, v1.x, acc.x); acc.y = fmaf(a1, v1.y, acc.y);
        acc.z = fmaf(a1, v1.z, acc.z); acc.w = fmaf(a1, v1.w, acc.w);
        attsum += a0 + a1;
    }
    if (e < end) {
        int   s0 = g_es[e];
        float a0 = g_ea[e];
        float4 v0 = sf4[(size_t)s0 * 32 + lane];
        acc.x = fmaf(a0, v0.x, acc.x); acc.y = fmaf(a0, v0.y, acc.y);
        acc.z = fmaf(a0, v0.z, acc.z); acc.w = fmaf(a0, v0.w, acc.w);
        attsum += a0;
    }

    float inv = 1.0f / fmaxf(attsum, 1e-8f);
    float4 r = make_float4(acc.x * inv, acc.y * inv, acc.z * inv, acc.w * inv);
    ((float4*)(out + (size_t)wid * DIMS))[lane] = r;
}

// ---------------------------------------------------------------------------
extern "C" void kernel_launch(void* const* d_in, const int* in_sizes, int n_in,
                              void* d_out, int out_size) {
    const float* src_feat   = (const float*)d_in[0];
    const float* dst_feat   = (const float*)d_in[1];
    const float* att_w      = (const float*)d_in[2];
    const float* att_b      = (const float*)d_in[3];
    const int*   edge_index = (const int*)d_in[4];

    int n_src   = in_sizes[0] / DIMS;
    int n_dst   = out_size    / DIMS;
    int n_edges = in_sizes[4] / 2;

    float* out = (float*)d_out;

    // Zero the degree histogram each call.
    void* counts_ptr = nullptr;
    cudaGetSymbolAddress(&counts_ptr, g_counts);
    cudaMemsetAsync(counts_ptr, 0, (size_t)n_dst * sizeof(int), 0);

    // K1: per-row dot products.
    {
        int warps = n_src + n_dst;
        int threads = 256;
        int blocks = (warps * 32 + threads - 1) / threads;
        dot_kernel<<<blocks, threads>>>(src_feat, dst_feat, att_w, att_b,
                                        n_src, n_dst);
    }

    // K2: dst-degree histogram.
    {
        int threads = 256;
        int blocks = (n_edges + threads - 1) / threads;
        hist_kernel<<<blocks, threads>>>(edge_index, n_edges);
    }

    // K3: exclusive scan -> offsets + cursor.
    scan_kernel<<<1, SCAN_THREADS>>>(n_dst);

    // K4: scatter edges into buckets with precomputed attention.
    {
        int threads = 256;
        int blocks = (n_edges + threads - 1) / threads;
        scatter_kernel<<<blocks, threads>>>(edge_index, n_edges);
    }

    // K5: warp-per-dst aggregate + normalize, single write to d_out.
    {
        int threads = 256;
        int warps_per_block = threads / 32;
        int blocks = (n_dst + warps_per_block - 1) / warps_per_block;
        agg_kernel<<<blocks, threads>>>(src_feat, out, n_dst);
    }
}

// round 5
// speedup vs baseline: 3.2235x; 2.1076x over previous
#include <cuda_runtime.h>
#include <cuda_bf16.h>

// Problem constants (fixed by reference setup_inputs):
//   src_feat [50000,128] f32, dst_feat [50000,128] f32,
//   att_w [256,1] f32, att_b [1] f32,
//   edge_index [2,640000] int32, n_dst scalar (derived from out_size).
#define DIMS 128
#define NMAX 53248     // slack over 50000, multiple of 4096
#define EMAX 700000
#define SCAN_TILE 4096
#define MAX_TILES 32   // 50000/4096 = 13 tiles; single-warp partial scan

__device__ float g_srcdot[NMAX];
__device__ float g_dstdot[NMAX];                 // includes +bias
__device__ __align__(16) int g_counts[NMAX];
__device__ __align__(16) int g_offsets[NMAX + 4];
__device__ __align__(16) int g_cursor[NMAX];
__device__ int   g_part[MAX_TILES];
__device__ int   g_partscan[MAX_TILES];
__device__ int2  g_pack[EMAX];                   // {src index, att bits}

// ---------------------------------------------------------------------------
// K1: fused per-row dots (warp per row) + dst-degree histogram.
// Blocks [0, dot_blocks) do dots; blocks [dot_blocks, ...) do histogram.
// ---------------------------------------------------------------------------
__global__ void prep_kernel(const float* __restrict__ src_feat,
                            const float* __restrict__ dst_feat,
                            const float* __restrict__ att_w,
                            const float* __restrict__ att_b,
                            const int* __restrict__ edge_index,
                            int n_src, int n_dst, int n_edges,
                            int dot_blocks) {
    if (blockIdx.x < (unsigned)dot_blocks) {
        int wid  = (blockIdx.x * blockDim.x + threadIdx.x) >> 5;
        int lane = threadIdx.x & 31;
        int total = n_src + n_dst;
        if (wid >= total) return;

        bool is_src = (wid < n_src);
        int row = is_src ? wid : (wid - n_src);
        const float* feat = is_src ? src_feat : dst_feat;
        const float* w    = att_w + (is_src ? 0 : DIMS);

        float4 f  = ((const float4*)(feat + (size_t)row * DIMS))[lane];
        float4 wv = ((const float4*)w)[lane];
        float s = f.x * wv.x + f.y * wv.y + f.z * wv.z + f.w * wv.w;

        #pragma unroll
        for (int o = 16; o > 0; o >>= 1)
            s += __shfl_down_sync(0xffffffffu, s, o);

        if (lane == 0) {
            if (is_src) g_srcdot[row] = s;
            else        g_dstdot[row] = s + att_b[0];
        }
    } else {
        int i = (blockIdx.x - dot_blocks) * blockDim.x + threadIdx.x;
        if (i >= n_edges) return;
        atomicAdd(&g_counts[edge_index[n_edges + i]], 1);
    }
}

// ---------------------------------------------------------------------------
// K2a: per-tile reduce of counts (coalesced).
// ---------------------------------------------------------------------------
__global__ void scan_reduce_kernel(int n_dst) {
    __shared__ int wsum[32];
    int b = blockIdx.x, t = threadIdx.x;
    int base = b * SCAN_TILE;

    int sum = 0;
    for (int i = t; i < SCAN_TILE; i += blockDim.x) {
        int idx = base + i;
        if (idx < n_dst) sum += g_counts[idx];
    }
    int lane = t & 31, w = t >> 5;
    #pragma unroll
    for (int o = 16; o > 0; o >>= 1)
        sum += __shfl_down_sync(0xffffffffu, sum, o);
    if (lane == 0) wsum[w] = sum;
    __syncthreads();
    if (w == 0) {
        int v = (lane < (int)(blockDim.x >> 5)) ? wsum[lane] : 0;
        #pragma unroll
        for (int o = 16; o > 0; o >>= 1)
            v += __shfl_down_sync(0xffffffffu, v, o);
        if (lane == 0) g_part[b] = v;
    }
}

// ---------------------------------------------------------------------------
// K2b: single-warp exclusive scan of tile partials; writes total sentinel.
// ---------------------------------------------------------------------------
__global__ void scan_part_kernel(int n_tiles, int n_dst) {
    int t = threadIdx.x;
    int v = (t < n_tiles) ? g_part[t] : 0;
    int incl = v;
    #pragma unroll
    for (int o = 1; o < 32; o <<= 1) {
        int y = __shfl_up_sync(0xffffffffu, incl, o);
        if (t >= o) incl += y;
    }
    if (t < n_tiles) g_partscan[t] = incl - v;
    int total = __shfl_sync(0xffffffffu, incl, 31);
    if (t == 0) g_offsets[n_dst] = total;
}

// ---------------------------------------------------------------------------
// K2c: per-tile local exclusive scan (int4, coalesced) -> offsets + cursor.
// Thread t owns elements [tile + 4t, tile + 4t + 4).
// ---------------------------------------------------------------------------
__global__ void scan_local_kernel(int n_dst) {
    __shared__ int wsum[32];
    int b = blockIdx.x, t = threadIdx.x;
    int base = b * SCAN_TILE + t * 4;

    int4 v = make_int4(0, 0, 0, 0);
    if (base + 3 < n_dst) {
        v = *(const int4*)&g_counts[base];
    } else {
        if (base + 0 < n_dst) v.x = g_counts[base + 0];
        if (base + 1 < n_dst) v.y = g_counts[base + 1];
        if (base + 2 < n_dst) v.z = g_counts[base + 2];
        if (base + 3 < n_dst) v.w = g_counts[base + 3];
    }
    int s0 = v.x, s1 = s0 + v.y, s2 = s1 + v.z, s3 = s2 + v.w;

    // block exclusive scan of per-thread totals (s3)
    int lane = t & 31, w = t >> 5;
    int incl = s3;
    #pragma unroll
    for (int o = 1; o < 32; o <<= 1) {
        int y = __shfl_up_sync(0xffffffffu, incl, o);
        if (lane >= o) incl += y;
    }
    if (lane == 31) wsum[w] = incl;
    __syncthreads();
    if (w == 0) {
        int x = (lane < (int)(blockDim.x >> 5)) ? wsum[lane] : 0;
        #pragma unroll
        for (int o = 1; o < 32; o <<= 1) {
            int y = __shfl_up_sync(0xffffffffu, x, o);
            if (lane >= o) x += y;
        }
        wsum[lane] = x;
    }
    __syncthreads();
    int prefix = (incl - s3) + (w > 0 ? wsum[w - 1] : 0) + g_partscan[b];

    int4 o4 = make_int4(prefix, prefix + s0, prefix + s1, prefix + s2);
    if (base + 3 < n_dst) {
        *(int4*)&g_offsets[base] = o4;
        *(int4*)&g_cursor[base]  = o4;
    } else {
        if (base + 0 < n_dst) { g_offsets[base + 0] = o4.x; g_cursor[base + 0] = o4.x; }
        if (base + 1 < n_dst) { g_offsets[base + 1] = o4.y; g_cursor[base + 1] = o4.y; }
        if (base + 2 < n_dst) { g_offsets[base + 2] = o4.z; g_cursor[base + 2] = o4.z; }
        if (base + 3 < n_dst) { g_offsets[base + 3] = o4.w; g_cursor[base + 3] = o4.w; }
    }
}

// ---------------------------------------------------------------------------
// K3: scatter edges into buckets. 4 edges per thread for MLP; packed payload.
// ---------------------------------------------------------------------------
__global__ void scatter_kernel(const int* __restrict__ edge_index, int n_edges) {
    int i0 = (blockIdx.x * blockDim.x + threadIdx.x) * 4;
    if (i0 >= n_edges) return;

    if (i0 + 4 <= n_edges && (n_edges & 3) == 0) {
        int4 s4 = *(const int4*)&edge_index[i0];
        int4 d4 = *(const int4*)&edge_index[n_edges + i0];

        // Issue all 8 gathers before consuming (MLP=8).
        float sa = g_srcdot[s4.x], sb = g_srcdot[s4.y];
        float sc = g_srcdot[s4.z], sd = g_srcdot[s4.w];
        float da = g_dstdot[d4.x], db = g_dstdot[d4.y];
        float dc = g_dstdot[d4.z], dd = g_dstdot[d4.w];

        float a0 = 1.0f / (1.0f + __expf(-(sa + da)));
        float a1 = 1.0f / (1.0f + __expf(-(sb + db)));
        float a2 = 1.0f / (1.0f + __expf(-(sc + dc)));
        float a3 = 1.0f / (1.0f + __expf(-(sd + dd)));

        int p0 = atomicAdd(&g_cursor[d4.x], 1);
        int p1 = atomicAdd(&g_cursor[d4.y], 1);
        int p2 = atomicAdd(&g_cursor[d4.z], 1);
        int p3 = atomicAdd(&g_cursor[d4.w], 1);

        g_pack[p0] = make_int2(s4.x, __float_as_int(a0));
        g_pack[p1] = make_int2(s4.y, __float_as_int(a1));
        g_pack[p2] = make_int2(s4.z, __float_as_int(a2));
        g_pack[p3] = make_int2(s4.w, __float_as_int(a3));
    } else {
        for (int i = i0; i < n_edges && i < i0 + 4; i++) {
            int s = edge_index[i];
            int d = edge_index[n_edges + i];
            float att = 1.0f / (1.0f + __expf(-(g_srcdot[s] + g_dstdot[d])));
            int pos = atomicAdd(&g_cursor[d], 1);
            g_pack[pos] = make_int2(s, __float_as_int(att));
        }
    }
}

// ---------------------------------------------------------------------------
// K4: warp-per-dst aggregation + fused normalize. 4-wide unroll for MLP.
// ---------------------------------------------------------------------------
__global__ void agg_kernel(const float* __restrict__ src_feat,
                           float* __restrict__ out, int n_dst) {
    int wid  = (blockIdx.x * blockDim.x + threadIdx.x) >> 5;
    int lane = threadIdx.x & 31;
    if (wid >= n_dst) return;

    int start = g_offsets[wid];
    int end   = g_offsets[wid + 1];

    float4 acc = make_float4(0.f, 0.f, 0.f, 0.f);
    float attsum = 0.f;
    const float4* sf4 = (const float4*)src_feat;

    int e = start;
    for (; e + 3 < end; e += 4) {
        int2 p0 = g_pack[e + 0];
        int2 p1 = g_pack[e + 1];
        int2 p2 = g_pack[e + 2];
        int2 p3 = g_pack[e + 3];
        float4 v0 = sf4[(size_t)p0.x * 32 + lane];
        float4 v1 = sf4[(size_t)p1.x * 32 + lane];
        float4 v2 = sf4[(size_t)p2.x * 32 + lane];
        float4 v3 = sf4[(size_t)p3.x * 32 + lane];
        float a0 = __int_as_float(p0.y), a1 = __int_as_float(p1.y);
        float a2 = __int_as_float(p2.y), a3 = __int_as_float(p3.y);
        acc.x = fmaf(a0, v0.x, acc.x); acc.y = fmaf(a0, v0.y, acc.y);
        acc.z = fmaf(a0, v0.z, acc.z); acc.w = fmaf(a0, v0.w, acc.w);
        acc.x = fmaf(a1, v1.x, acc.x); acc.y = fmaf(a1, v1.y, acc.y);
        acc.z = fmaf(a1, v1.z, acc.z); acc.w = fmaf(a1, v1.w, acc.w);
        acc.x = fmaf(a2, v2.x, acc.x); acc.y = fmaf(a2, v2.y, acc.y);
        acc.z = fmaf(a2, v2.z, acc.z); acc.w = fmaf(a2, v2.w, acc.w);
        acc.x = fmaf(a3, v3.x, acc.x); acc.y = fmaf(a3, v3.y, acc.y);
        acc.z = fmaf(a3, v3.z, acc.z); acc.w = fmaf(a3, v3.w, acc.w);
        attsum += (a0 + a1) + (a2 + a3);
    }
    for (; e < end; e++) {
        int2 p = g_pack[e];
        float a = __int_as_float(p.y);
        float4 v = sf4[(size_t)p.x * 32 + lane];
        acc.x = fmaf(a, v.x, acc.x); acc.y = fmaf(a, v.y, acc.y);
        acc.z = fmaf(a, v.z, acc.z); acc.w = fmaf(a, v.w, acc.w);
        attsum += a;
    }

    float inv = 1.0f / fmaxf(attsum, 1e-8f);
    float4 r = make_float4(acc.x * inv, acc.y * inv, acc.z * inv, acc.w * inv);
    ((float4*)(out + (size_t)wid * DIMS))[lane] = r;
}

// ---------------------------------------------------------------------------
extern "C" void kernel_launch(void* const* d_in, const int* in_sizes, int n_in,
                              void* d_out, int out_size) {
    const float* src_feat   = (const float*)d_in[0];
    const float* dst_feat   = (const float*)d_in[1];
    const float* att_w      = (const float*)d_in[2];
    const float* att_b      = (const float*)d_in[3];
    const int*   edge_index = (const int*)d_in[4];

    int n_src   = in_sizes[0] / DIMS;
    int n_dst   = out_size    / DIMS;
    int n_edges = in_sizes[4] / 2;

    float* out = (float*)d_out;

    void* counts_ptr = nullptr;
    cudaGetSymbolAddress(&counts_ptr, g_counts);
    cudaMemsetAsync(counts_ptr, 0, (size_t)n_dst * sizeof(int), 0);

    // K1: fused dots + histogram.
    {
        int threads = 256;
        int dot_blocks  = ((n_src + n_dst) * 32 + threads - 1) / threads;
        int hist_blocks = (n_edges + threads - 1) / threads;
        prep_kernel<<<dot_blocks + hist_blocks, threads>>>(
            src_feat, dst_feat, att_w, att_b, edge_index,
            n_src, n_dst, n_edges, dot_blocks);
    }

    // K2: coalesced 3-phase scan.
    int n_tiles = (n_dst + SCAN_TILE - 1) / SCAN_TILE;
    scan_reduce_kernel<<<n_tiles, 1024>>>(n_dst);
    scan_part_kernel<<<1, 32>>>(n_tiles, n_dst);
    scan_local_kernel<<<n_tiles, 1024>>>(n_dst);

    // K3: scatter (4 edges per thread).
    {
        int threads = 256;
        int blocks = (n_edges + threads * 4 - 1) / (threads * 4);
        scatter_kernel<<<blocks, threads>>>(edge_index, n_edges);
    }

    // K4: warp-per-dst aggregate + normalize.
    {
        int threads = 256;
        int warps_per_block = threads / 32;
        int blocks = (n_dst + warps_per_block - 1) / warps_per_block;
        agg_kernel<<<blocks, threads>>>(src_feat, out, n_dst);
    }
}

// round 6
// speedup vs baseline: 3.4732x; 1.0775x over previous
#include <cuda_runtime.h>
#include <cuda_bf16.h>

// Problem constants (fixed by reference setup_inputs):
//   src_feat [50000,128] f32, dst_feat [50000,128] f32,
//   att_w [256,1] f32, att_b [1] f32,
//   edge_index [2,640000] int32, n_dst scalar (derived from out_size).
#define DIMS 128
#define NMAX 53248     // slack over 50000, multiple of 4096
#define EMAX 700000
#define SCAN_TILE 4096

__device__ float g_srcdot[NMAX];
__device__ float g_dstdot[NMAX];                 // includes +bias
__device__ __align__(16) int g_counts[NMAX];
__device__ __align__(16) int g_offsets[NMAX + 4];
__device__ __align__(16) int g_cursor[NMAX];
__device__ int2  g_pack[EMAX];                   // {src index, att bits}

// ---------------------------------------------------------------------------
// K1: fused per-row dots (4 rows per warp, weights loaded once) + histogram.
// Blocks [0, dot_blocks) do dots; blocks [dot_blocks, ...) do histogram.
// ---------------------------------------------------------------------------
__global__ void prep_kernel(const float* __restrict__ src_feat,
                            const float* __restrict__ dst_feat,
                            const float* __restrict__ att_w,
                            const float* __restrict__ att_b,
                            const int* __restrict__ edge_index,
                            int n_src, int n_dst, int n_edges,
                            int dot_blocks) {
    if (blockIdx.x < (unsigned)dot_blocks) {
        int gw   = (blockIdx.x * blockDim.x + threadIdx.x) >> 5;
        int lane = threadIdx.x & 31;
        int total = n_src + n_dst;
        int base = gw * 4;
        if (base >= total) return;

        // Weight halves: loaded once per warp (L1-resident).
        float4 wv_s = ((const float4*)att_w)[lane];
        float4 wv_d = ((const float4*)(att_w + DIMS))[lane];
        float bias = att_b[0];

        // Issue all 4 feature-row loads up front (MLP=4).
        float4 f[4];
        #pragma unroll
        for (int r = 0; r < 4; r++) {
            int row = base + r;
            if (row < total) {
                const float* feat = (row < n_src)
                    ? (src_feat + (size_t)row * DIMS)
                    : (dst_feat + (size_t)(row - n_src) * DIMS);
                f[r] = ((const float4*)feat)[lane];
            } else {
                f[r] = make_float4(0.f, 0.f, 0.f, 0.f);
            }
        }

        #pragma unroll
        for (int r = 0; r < 4; r++) {
            int row = base + r;
            if (row >= total) break;
            bool is_src = (row < n_src);
            float4 wv = is_src ? wv_s : wv_d;
            float s = f[r].x * wv.x + f[r].y * wv.y
                    + f[r].z * wv.z + f[r].w * wv.w;
            #pragma unroll
            for (int o = 16; o > 0; o >>= 1)
                s += __shfl_down_sync(0xffffffffu, s, o);
            if (lane == 0) {
                if (is_src) g_srcdot[row] = s;
                else        g_dstdot[row - n_src] = s + bias;
            }
        }
    } else {
        int i = (blockIdx.x - dot_blocks) * blockDim.x + threadIdx.x;
        if (i >= n_edges) return;
        atomicAdd(&g_counts[edge_index[n_edges + i]], 1);
    }
}

// ---------------------------------------------------------------------------
// K2: single-kernel scan. Block b:
//   phase 1: block-reduce counts[0 .. b*SCAN_TILE) -> tile prefix (redundant
//            across blocks, but coalesced and tiny: <= 48k ints).
//   phase 2: int4 local exclusive scan of its own tile -> offsets + cursor.
// Last block writes the total sentinel g_offsets[n_dst].
// ---------------------------------------------------------------------------
__global__ void scan_kernel(int n_dst, int n_tiles) {
    __shared__ int wsum[32];
    __shared__ int s_prefix;
    int b = blockIdx.x, t = threadIdx.x;
    int lane = t & 31, w = t >> 5;
    int nwarps = blockDim.x >> 5;

    // ---- phase 1: prefix = sum over preceding tiles ----
    int pre = 0;
    {
        int limit4 = (b * SCAN_TILE) >> 2;           // preceding tiles are full
        const int4* c4 = (const int4*)g_counts;
        for (int i = t; i < limit4; i += blockDim.x) {
            int4 v = c4[i];
            pre += v.x + v.y + v.z + v.w;
        }
        #pragma unroll
        for (int o = 16; o > 0; o >>= 1)
            pre += __shfl_down_sync(0xffffffffu, pre, o);
        if (lane == 0) wsum[w] = pre;
        __syncthreads();
        if (w == 0) {
            int v = (lane < nwarps) ? wsum[lane] : 0;
            #pragma unroll
            for (int o = 16; o > 0; o >>= 1)
                v += __shfl_down_sync(0xffffffffu, v, o);
            if (lane == 0) s_prefix = v;
        }
        __syncthreads();
    }
    int tile_prefix = s_prefix;
    __syncthreads();   // wsum reused below

    // ---- phase 2: local exclusive scan of own tile ----
    int base = b * SCAN_TILE + t * 4;
    int4 v = make_int4(0, 0, 0, 0);
    if (base + 3 < n_dst) {
        v = *(const int4*)&g_counts[base];
    } else {
        if (base + 0 < n_dst) v.x = g_counts[base + 0];
        if (base + 1 < n_dst) v.y = g_counts[base + 1];
        if (base + 2 < n_dst) v.z = g_counts[base + 2];
        if (base + 3 < n_dst) v.w = g_counts[base + 3];
    }
    int s0 = v.x, s1 = s0 + v.y, s2 = s1 + v.z, s3 = s2 + v.w;

    int incl = s3;
    #pragma unroll
    for (int o = 1; o < 32; o <<= 1) {
        int y = __shfl_up_sync(0xffffffffu, incl, o);
        if (lane >= o) incl += y;
    }
    if (lane == 31) wsum[w] = incl;
    __syncthreads();
    if (w == 0) {
        int x = (lane < nwarps) ? wsum[lane] : 0;
        #pragma unroll
        for (int o = 1; o < 32; o <<= 1) {
            int y = __shfl_up_sync(0xffffffffu, x, o);
            if (lane >= o) x += y;
        }
        wsum[lane] = x;
    }
    __syncthreads();
    int prefix = (incl - s3) + (w > 0 ? wsum[w - 1] : 0) + tile_prefix;

    int4 o4 = make_int4(prefix, prefix + s0, prefix + s1, prefix + s2);
    if (base + 3 < n_dst) {
        *(int4*)&g_offsets[base] = o4;
        *(int4*)&g_cursor[base]  = o4;
    } else {
        if (base + 0 < n_dst) { g_offsets[base + 0] = o4.x; g_cursor[base + 0] = o4.x; }
        if (base + 1 < n_dst) { g_offsets[base + 1] = o4.y; g_cursor[base + 1] = o4.y; }
        if (base + 2 < n_dst) { g_offsets[base + 2] = o4.z; g_cursor[base + 2] = o4.z; }
        if (base + 3 < n_dst) { g_offsets[base + 3] = o4.w; g_cursor[base + 3] = o4.w; }
    }

    // sentinel: total edge count (last block, one thread)
    if (b == n_tiles - 1 && t == 0)
        g_offsets[n_dst] = tile_prefix + wsum[nwarps - 1];
}

// ---------------------------------------------------------------------------
// K3: scatter edges into buckets. 4 edges per thread for MLP; packed payload.
// ---------------------------------------------------------------------------
__global__ void scatter_kernel(const int* __restrict__ edge_index, int n_edges) {
    int i0 = (blockIdx.x * blockDim.x + threadIdx.x) * 4;
    if (i0 >= n_edges) return;

    if (i0 + 4 <= n_edges && (n_edges & 3) == 0) {
        int4 s4 = *(const int4*)&edge_index[i0];
        int4 d4 = *(const int4*)&edge_index[n_edges + i0];

        float sa = g_srcdot[s4.x], sb = g_srcdot[s4.y];
        float sc = g_srcdot[s4.z], sd = g_srcdot[s4.w];
        float da = g_dstdot[d4.x], db = g_dstdot[d4.y];
        float dc = g_dstdot[d4.z], dd = g_dstdot[d4.w];

        float a0 = 1.0f / (1.0f + __expf(-(sa + da)));
        float a1 = 1.0f / (1.0f + __expf(-(sb + db)));
        float a2 = 1.0f / (1.0f + __expf(-(sc + dc)));
        float a3 = 1.0f / (1.0f + __expf(-(sd + dd)));

        int p0 = atomicAdd(&g_cursor[d4.x], 1);
        int p1 = atomicAdd(&g_cursor[d4.y], 1);
        int p2 = atomicAdd(&g_cursor[d4.z], 1);
        int p3 = atomicAdd(&g_cursor[d4.w], 1);

        g_pack[p0] = make_int2(s4.x, __float_as_int(a0));
        g_pack[p1] = make_int2(s4.y, __float_as_int(a1));
        g_pack[p2] = make_int2(s4.z, __float_as_int(a2));
        g_pack[p3] = make_int2(s4.w, __float_as_int(a3));
    } else {
        for (int i = i0; i < n_edges && i < i0 + 4; i++) {
            int s = edge_index[i];
            int d = edge_index[n_edges + i];
            float att = 1.0f / (1.0f + __expf(-(g_srcdot[s] + g_dstdot[d])));
            int pos = atomicAdd(&g_cursor[d], 1);
            g_pack[pos] = make_int2(s, __float_as_int(att));
        }
    }
}

// ---------------------------------------------------------------------------
// K4: warp-per-dst aggregation + fused normalize. 4-wide unroll for MLP.
// ---------------------------------------------------------------------------
__global__ void agg_kernel(const float* __restrict__ src_feat,
                           float* __restrict__ out, int n_dst) {
    int wid  = (blockIdx.x * blockDim.x + threadIdx.x) >> 5;
    int lane = threadIdx.x & 31;
    if (wid >= n_dst) return;

    int start = g_offsets[wid];
    int end   = g_offsets[wid + 1];

    float4 acc = make_float4(0.f, 0.f, 0.f, 0.f);
    float attsum = 0.f;
    const float4* sf4 = (const float4*)src_feat;

    int e = start;
    for (; e + 3 < end; e += 4) {
        int2 p0 = g_pack[e + 0];
        int2 p1 = g_pack[e + 1];
        int2 p2 = g_pack[e + 2];
        int2 p3 = g_pack[e + 3];
        float4 v0 = sf4[(size_t)p0.x * 32 + lane];
        float4 v1 = sf4[(size_t)p1.x * 32 + lane];
        float4 v2 = sf4[(size_t)p2.x * 32 + lane];
        float4 v3 = sf4[(size_t)p3.x * 32 + lane];
        float a0 = __int_as_float(p0.y), a1 = __int_as_float(p1.y);
        float a2 = __int_as_float(p2.y), a3 = __int_as_float(p3.y);
        acc.x = fmaf(a0, v0.x, acc.x); acc.y = fmaf(a0, v0.y, acc.y);
        acc.z = fmaf(a0, v0.z, acc.z); acc.w = fmaf(a0, v0.w, acc.w);
        acc.x = fmaf(a1, v1.x, acc.x); acc.y = fmaf(a1, v1.y, acc.y);
        acc.z = fmaf(a1, v1.z, acc.z); acc.w = fmaf(a1, v1.w, acc.w);
        acc.x = fmaf(a2, v2.x, acc.x); acc.y = fmaf(a2, v2.y, acc.y);
        acc.z = fmaf(a2, v2.z, acc.z); acc.w = fmaf(a2, v2.w, acc.w);
        acc.x = fmaf(a3, v3.x, acc.x); acc.y = fmaf(a3, v3.y, acc.y);
        acc.z = fmaf(a3, v3.z, acc.z); acc.w = fmaf(a3, v3.w, acc.w);
        attsum += (a0 + a1) + (a2 + a3);
    }
    for (; e < end; e++) {
        int2 p = g_pack[e];
        float a = __int_as_float(p.y);
        float4 v = sf4[(size_t)p.x * 32 + lane];
        acc.x = fmaf(a, v.x, acc.x); acc.y = fmaf(a, v.y, acc.y);
        acc.z = fmaf(a, v.z, acc.z); acc.w = fmaf(a, v.w, acc.w);
        attsum += a;
    }

    float inv = 1.0f / fmaxf(attsum, 1e-8f);
    float4 r = make_float4(acc.x * inv, acc.y * inv, acc.z * inv, acc.w * inv);
    ((float4*)(out + (size_t)wid * DIMS))[lane] = r;
}

// ---------------------------------------------------------------------------
extern "C" void kernel_launch(void* const* d_in, const int* in_sizes, int n_in,
                              void* d_out, int out_size) {
    const float* src_feat   = (const float*)d_in[0];
    const float* dst_feat   = (const float*)d_in[1];
    const float* att_w      = (const float*)d_in[2];
    const float* att_b      = (const float*)d_in[3];
    const int*   edge_index = (const int*)d_in[4];

    int n_src   = in_sizes[0] / DIMS;
    int n_dst   = out_size    / DIMS;
    int n_edges = in_sizes[4] / 2;

    float* out = (float*)d_out;

    void* counts_ptr = nullptr;
    cudaGetSymbolAddress(&counts_ptr, g_counts);
    cudaMemsetAsync(counts_ptr, 0, (size_t)n_dst * sizeof(int), 0);

    // K1: fused dots (4 rows/warp) + histogram.
    {
        int threads = 256;
        int total = n_src + n_dst;
        int dot_warps = (total + 3) / 4;
        int dot_blocks  = (dot_warps * 32 + threads - 1) / threads;
        int hist_blocks = (n_edges + threads - 1) / threads;
        prep_kernel<<<dot_blocks + hist_blocks, threads>>>(
            src_feat, dst_feat, att_w, att_b, edge_index,
            n_src, n_dst, n_edges, dot_blocks);
    }

    // K2: single-kernel scan.
    int n_tiles = (n_dst + SCAN_TILE - 1) / SCAN_TILE;
    scan_kernel<<<n_tiles, 1024>>>(n_dst, n_tiles);

    // K3: scatter (4 edges per thread).
    {
        int threads = 256;
        int blocks = (n_edges + threads * 4 - 1) / (threads * 4);
        scatter_kernel<<<blocks, threads>>>(edge_index, n_edges);
    }

    // K4: warp-per-dst aggregate + normalize.
    {
        int threads = 256;
        int warps_per_block = threads / 32;
        int blocks = (n_dst + warps_per_block - 1) / warps_per_block;
        agg_kernel<<<blocks, threads>>>(src_feat, out, n_dst);
    }
}